// round 1
// baseline (speedup 1.0000x reference)
#include <cuda_runtime.h>
#include <stdint.h>

#define N_TOKENS 131072
#define D_MODEL  512
#define PATHS    16
#define CAP      16384                 // 2 * N / P
#define D4       (D_MODEL / 4)         // 128 float4 per row

#define CHUNK    256                   // tokens per warp-chunk
#define WARPS_PB 8
#define NCHUNK   (N_TOKENS / CHUNK)    // 512
#define GRID1    (NCHUNK / WARPS_PB)   // 64

// ---- scratch (no allocations allowed) ----
__device__ uint8_t g_idx[N_TOKENS];          // argmax path per token
__device__ int     g_hist[NCHUNK * PATHS];   // per-chunk histograms
__device__ int     g_base[NCHUNK * PATHS];   // exclusive prefix per chunk/path
__device__ int     g_cnt[PATHS];             // per-path count, clamped to CAP
__device__ int     g_slot[PATHS * CAP];      // slot -> token gather map

// Pass 1: per-token argmax over 16 scores + per-chunk histogram (no atomics).
__global__ __launch_bounds__(256) void k_argmax_hist(const float* __restrict__ score) {
    __shared__ int sh[WARPS_PB][PATHS];
    const int tid = threadIdx.x, w = tid >> 5, lane = tid & 31;
    const int c = blockIdx.x * WARPS_PB + w;
    if (lane < PATHS) sh[w][lane] = 0;
    __syncwarp();
    const int tok0 = c * CHUNK;
    #pragma unroll 1
    for (int s = 0; s < CHUNK / 32; s++) {
        const int tok = tok0 + s * 32 + lane;
        const float4* sc = (const float4*)(score + (size_t)tok * PATHS);
        float4 a = sc[0], b = sc[1], cc = sc[2], d = sc[3];
        float v[16] = {a.x,a.y,a.z,a.w, b.x,b.y,b.z,b.w,
                       cc.x,cc.y,cc.z,cc.w, d.x,d.y,d.z,d.w};
        int best = 0; float bv = v[0];
        #pragma unroll
        for (int p = 1; p < 16; p++) if (v[p] > bv) { bv = v[p]; best = p; }   // first-max (jnp.argmax)
        g_idx[tok] = (uint8_t)best;
        unsigned m = __match_any_sync(0xffffffffu, best);
        if ((__ffs(m) - 1) == lane) sh[w][best] += __popc(m);  // unique leader per path
        __syncwarp();
    }
    if (lane < PATHS) g_hist[c * PATHS + lane] = sh[w][lane];
}

// Pass 2: exclusive scan of chunk histograms (single block, via shared).
__global__ __launch_bounds__(256) void k_scan() {
    __shared__ int sh[NCHUNK * PATHS];   // 32 KB
    for (int i = threadIdx.x; i < NCHUNK * PATHS; i += blockDim.x) sh[i] = g_hist[i];
    __syncthreads();
    if (threadIdx.x < PATHS) {
        const int p = threadIdx.x;
        int run = 0;
        #pragma unroll 4
        for (int c = 0; c < NCHUNK; c++) {
            int v = sh[c * PATHS + p];
            sh[c * PATHS + p] = run;
            run += v;
        }
        g_cnt[p] = run < CAP ? run : CAP;
    }
    __syncthreads();
    for (int i = threadIdx.x; i < NCHUNK * PATHS; i += blockDim.x) g_base[i] = sh[i];
}

// Pass 3: order-preserving positions; build slot->token gather map.
__global__ __launch_bounds__(256) void k_pos() {
    __shared__ int sh[WARPS_PB][PATHS];
    const int tid = threadIdx.x, w = tid >> 5, lane = tid & 31;
    const int c = blockIdx.x * WARPS_PB + w;
    if (lane < PATHS) sh[w][lane] = g_base[c * PATHS + lane];
    __syncwarp();
    const int tok0 = c * CHUNK;
    #pragma unroll 1
    for (int s = 0; s < CHUNK / 32; s++) {
        const int tok = tok0 + s * 32 + lane;
        const int p = (int)g_idx[tok];
        unsigned m = __match_any_sync(0xffffffffu, p);
        const int rank = __popc(m & ((1u << lane) - 1u));     // lanes below me, same path
        const int base = sh[w][p];                            // smem broadcast, all group lanes
        __syncwarp();
        if (lane == 31 - __clz(m)) sh[w][p] = base + __popc(m);  // max lane updates counter
        __syncwarp();
        const int pos = base + rank;
        if (pos < CAP) g_slot[p * CAP + pos] = tok;
    }
}

// Pass 4: write the whole output exactly once (copy routed rows, zero the rest).
#define ROWS_PB 4
__global__ __launch_bounds__(512) void k_gather(const float4* __restrict__ in4,
                                                float4* __restrict__ out4) {
    const int tid = threadIdx.x;
    const int r  = blockIdx.x * ROWS_PB + (tid >> 7);   // output row in [0, P*CAP)
    const int t  = tid & 127;                           // float4 index within row
    const int p  = r >> 14;                             // r / CAP
    const int j  = r & (CAP - 1);                       // r % CAP
    float4 v = make_float4(0.f, 0.f, 0.f, 0.f);
    if (j < g_cnt[p]) {
        const int i = g_slot[r];
        v = in4[(size_t)i * D4 + t];
    }
    out4[(size_t)r * D4 + t] = v;
}

extern "C" void kernel_launch(void* const* d_in, const int* in_sizes, int n_in,
                              void* d_out, int out_size) {
    const float* inputs = (const float*)d_in[0];
    const float* score  = (const float*)d_in[1];
    // defensive: identify by element count
    if (in_sizes[0] == N_TOKENS * PATHS) {
        inputs = (const float*)d_in[1];
        score  = (const float*)d_in[0];
    }
    k_argmax_hist<<<GRID1, 256>>>(score);
    k_scan<<<1, 256>>>();
    k_pos<<<GRID1, 256>>>();
    k_gather<<<(PATHS * CAP) / ROWS_PB, 512>>>((const float4*)inputs, (float4*)d_out);
}

// round 2
// speedup vs baseline: 1.2062x; 1.2062x over previous
#include <cuda_runtime.h>
#include <stdint.h>

#define N_TOKENS 131072
#define D_MODEL  512
#define PATHS    16
#define CAP      16384                 // 2 * N / P
#define D4       (D_MODEL / 4)         // 128 float4 per row

#define CHUNK    64                    // tokens per warp-chunk
#define WARPS_PB 8
#define NCHUNK   (N_TOKENS / CHUNK)    // 2048
#define GRID1    (NCHUNK / WARPS_PB)   // 256
#define SEGS     64                    // scan segments
#define SEGLEN   (NCHUNK / SEGS)       // 32 chunks per segment

// ---- scratch (no allocations allowed) ----
__device__ uint8_t g_idx[N_TOKENS];          // argmax path per token
__device__ int     g_hist[NCHUNK * PATHS];   // per-chunk histograms
__device__ int     g_base[NCHUNK * PATHS];   // exclusive prefix per chunk/path
__device__ int     g_cnt[PATHS];             // per-path count, clamped to CAP
__device__ int     g_slot[PATHS * CAP];      // slot -> token gather map

// Pass 1: per-token argmax over 16 scores + per-chunk histogram (no atomics).
__global__ __launch_bounds__(256) void k_argmax_hist(const float* __restrict__ score) {
    __shared__ int sh[WARPS_PB][PATHS];
    const int tid = threadIdx.x, w = tid >> 5, lane = tid & 31;
    const int c = blockIdx.x * WARPS_PB + w;
    if (lane < PATHS) sh[w][lane] = 0;
    __syncwarp();
    const int tok0 = c * CHUNK;
    #pragma unroll
    for (int s = 0; s < CHUNK / 32; s++) {
        const int tok = tok0 + s * 32 + lane;
        const float4* sc = (const float4*)(score + (size_t)tok * PATHS);
        float4 a = sc[0], b = sc[1], cc = sc[2], d = sc[3];
        float v[16] = {a.x,a.y,a.z,a.w, b.x,b.y,b.z,b.w,
                       cc.x,cc.y,cc.z,cc.w, d.x,d.y,d.z,d.w};
        int best = 0; float bv = v[0];
        #pragma unroll
        for (int p = 1; p < 16; p++) if (v[p] > bv) { bv = v[p]; best = p; }   // first-max (jnp.argmax)
        g_idx[tok] = (uint8_t)best;
        unsigned m = __match_any_sync(0xffffffffu, best);
        if ((__ffs(m) - 1) == lane) sh[w][best] += __popc(m);  // unique leader per path
        __syncwarp();
    }
    if (lane < PATHS) g_hist[c * PATHS + lane] = sh[w][lane];
}

// Pass 2: two-level exclusive scan of chunk histograms (single block, 1024 thr).
// Thread (p, s) owns segment s of path p (SEGLEN chunks).
__global__ __launch_bounds__(1024) void k_scan() {
    __shared__ int seg[PATHS][SEGS];     // segment sums -> segment bases
    const int tid = threadIdx.x;
    const int p = tid & (PATHS - 1);
    const int s = tid >> 4;              // 0..63
    // level 1: segment sums (coalesced: consecutive tid -> consecutive addr)
    int sum = 0;
    const int c0 = s * SEGLEN;
    #pragma unroll
    for (int c = 0; c < SEGLEN; c++) sum += g_hist[(c0 + c) * PATHS + p];
    seg[p][s] = sum;
    __syncthreads();
    // level 2: 16 threads scan 64 segments each
    if (tid < PATHS) {
        int run = 0;
        #pragma unroll
        for (int i = 0; i < SEGS; i++) {
            int v = seg[tid][i];
            seg[tid][i] = run;
            run += v;
        }
        g_cnt[tid] = run < CAP ? run : CAP;
    }
    __syncthreads();
    // level 3: expand within segment
    int run = seg[p][s];
    #pragma unroll
    for (int c = 0; c < SEGLEN; c++) {
        const int i = (c0 + c) * PATHS + p;
        int v = g_hist[i];
        g_base[i] = run;
        run += v;
    }
}

// Pass 3: order-preserving positions; build slot->token gather map.
__global__ __launch_bounds__(256) void k_pos() {
    __shared__ int sh[WARPS_PB][PATHS];
    const int tid = threadIdx.x, w = tid >> 5, lane = tid & 31;
    const int c = blockIdx.x * WARPS_PB + w;
    if (lane < PATHS) sh[w][lane] = g_base[c * PATHS + lane];
    __syncwarp();
    const int tok0 = c * CHUNK;
    #pragma unroll
    for (int s = 0; s < CHUNK / 32; s++) {
        const int tok = tok0 + s * 32 + lane;
        const int p = (int)g_idx[tok];
        unsigned m = __match_any_sync(0xffffffffu, p);
        const int rank = __popc(m & ((1u << lane) - 1u));     // lanes below me, same path
        const int base = sh[w][p];                            // smem broadcast
        __syncwarp();
        if (lane == 31 - __clz(m)) sh[w][p] = base + __popc(m);  // max lane updates counter
        __syncwarp();
        const int pos = base + rank;
        if (pos < CAP) g_slot[p * CAP + pos] = tok;
    }
}

// Pass 4: one warp per output row, 4 independent float4s per lane (MLP=4).
#define GROWS_PB 16
__global__ __launch_bounds__(512) void k_gather(const float4* __restrict__ in4,
                                                float4* __restrict__ out4) {
    const int w = threadIdx.x >> 5, lane = threadIdx.x & 31;
    const int r = blockIdx.x * GROWS_PB + w;            // output row in [0, P*CAP)
    const int p = r >> 14;                              // r / CAP
    const int j = r & (CAP - 1);                        // r % CAP
    float4 v0 = make_float4(0.f,0.f,0.f,0.f);
    float4 v1 = v0, v2 = v0, v3 = v0;
    if (j < g_cnt[p]) {
        const size_t base = (size_t)g_slot[r] * D4 + lane;
        const float4* src = in4 + base;
        v0 = src[0];
        v1 = src[32];
        v2 = src[64];
        v3 = src[96];
    }
    float4* dst = out4 + (size_t)r * D4 + lane;
    dst[0]  = v0;
    dst[32] = v1;
    dst[64] = v2;
    dst[96] = v3;
}

extern "C" void kernel_launch(void* const* d_in, const int* in_sizes, int n_in,
                              void* d_out, int out_size) {
    const float* inputs = (const float*)d_in[0];
    const float* score  = (const float*)d_in[1];
    if (in_sizes[0] == N_TOKENS * PATHS) {   // defensive: identify by element count
        inputs = (const float*)d_in[1];
        score  = (const float*)d_in[0];
    }
    k_argmax_hist<<<GRID1, 256>>>(score);
    k_scan<<<1, 1024>>>();
    k_pos<<<GRID1, 256>>>();
    k_gather<<<(PATHS * CAP) / GROWS_PB, 512>>>((const float4*)inputs, (float4*)d_out);
}

// round 4
// speedup vs baseline: 1.2296x; 1.0194x over previous
#include <cuda_runtime.h>
#include <stdint.h>

#define N_TOKENS 131072
#define D_MODEL  512
#define PATHS    16
#define CAP      16384                 // 2 * N / P
#define D4       (D_MODEL / 4)         // 128 float4 per row

#define NB       256                   // routing blocks
#define TPB      256                   // 8 warps
#define TOK_PER_WARP 64
#define TOK_PER_BLK  512               // NB * 512 = 131072

#define AGGF    0x40000000u
#define PREFIXF 0x80000000u
#define VALM    0x00FFFFFFu

// ---- scratch (no allocations allowed; zero-initialized at load) ----
__device__ int      g_cnt[PATHS];          // per-path count, clamped to CAP
__device__ int      g_slot[PATHS * CAP];   // slot -> token gather map
__device__ unsigned g_desc[NB * PATHS];    // decoupled-lookback descriptors
__device__ unsigned g_done;                // completion counter (self-resets)

__device__ __forceinline__ unsigned vload(const unsigned* p) {
    return *(volatile const unsigned*)p;
}

// Fused: argmax + per-warp histogram + block scan + decoupled-lookback global
// scan + order-preserving position assignment -> slot map. Single launch.
__global__ __launch_bounds__(TPB) void k_route(const float* __restrict__ score) {
    __shared__ uint8_t sh_pid[TOK_PER_BLK];
    __shared__ int sh_cnt[8][PATHS];
    __shared__ int sh_wexcl[8][PATHS];
    __shared__ int sh_agg[PATHS];
    __shared__ int sh_excl[PATHS];
    __shared__ int sh_run[8][PATHS];
    __shared__ int sh_last;
    const int tid = threadIdx.x, w = tid >> 5, lane = tid & 31, bid = blockIdx.x;
    const int blk0 = bid * TOK_PER_BLK;

    // ---- phase 1: argmax + per-warp per-path counts ----
    if (lane < PATHS) sh_cnt[w][lane] = 0;
    __syncwarp();
    #pragma unroll
    for (int g = 0; g < 2; g++) {
        const int li = w * TOK_PER_WARP + g * 32 + lane;
        const float4* sc = (const float4*)(score + (size_t)(blk0 + li) * PATHS);
        float4 a = __ldcs(sc), b = __ldcs(sc + 1), c = __ldcs(sc + 2), d = __ldcs(sc + 3);
        float v[16] = {a.x,a.y,a.z,a.w, b.x,b.y,b.z,b.w,
                       c.x,c.y,c.z,c.w, d.x,d.y,d.z,d.w};
        int best = 0; float bv = v[0];
        #pragma unroll
        for (int p = 1; p < 16; p++) if (v[p] > bv) { bv = v[p]; best = p; }  // first-max
        sh_pid[li] = (uint8_t)best;
        unsigned m = __match_any_sync(0xffffffffu, best);
        if ((__ffs(m) - 1) == lane) sh_cnt[w][best] += __popc(m);
        __syncwarp();
    }
    __syncthreads();

    // ---- block-local scan over 8 warps + early aggregate publish ----
    if (w == 0 && lane < PATHS) {
        int run = 0;
        #pragma unroll
        for (int ww = 0; ww < 8; ww++) { int v = sh_cnt[ww][lane]; sh_wexcl[ww][lane] = run; run += v; }
        sh_agg[lane] = run;
        unsigned pub = (bid == 0) ? ((unsigned)run | PREFIXF) : ((unsigned)run | AGGF);
        atomicExch(&g_desc[bid * PATHS + lane], pub);
    }
    __syncthreads();

    // ---- warp-windowed decoupled lookback: warp w owns paths w and w+8 ----
    #pragma unroll
    for (int q = 0; q < 2; q++) {
        const int p = w + q * 8;
        int excl = 0;
        if (bid > 0) {
            int j = bid - 1;
            while (true) {
                const int idx = j - lane;                  // lane 0 = nearest predecessor
                unsigned v = (idx >= 0) ? vload(&g_desc[idx * PATHS + p]) : PREFIXF;
                unsigned bP = __ballot_sync(0xffffffffu, (v & PREFIXF) != 0);
                unsigned bN = __ballot_sync(0xffffffffu, (v & (PREFIXF | AGGF)) == 0);
                int fP = bP ? (__ffs(bP) - 1) : 32;
                int fN = bN ? (__ffs(bN) - 1) : 32;
                if (fP < fN) {                             // prefix found before any gap
                    int add = (lane <= fP) ? (int)(v & VALM) : 0;
                    excl += __reduce_add_sync(0xffffffffu, add);
                    break;
                } else {                                   // consume ready AGGs (fN may be 32)
                    int add = (lane < fN) ? (int)(v & VALM) : 0;
                    excl += __reduce_add_sync(0xffffffffu, add);
                    j -= fN;                               // fN==0 -> spin on same window
                }
            }
            if (lane == 0)
                atomicExch(&g_desc[bid * PATHS + p], (unsigned)(excl + sh_agg[p]) | PREFIXF);
        }
        if (lane == 0) {
            sh_excl[p] = excl;
            if (bid == NB - 1) { int tot = excl + sh_agg[p]; g_cnt[p] = tot < CAP ? tot : CAP; }
        }
    }
    __syncthreads();

    // ---- phase 2: order-preserving rank -> slot map ----
    if (lane < PATHS) sh_run[w][lane] = sh_excl[lane] + sh_wexcl[w][lane];
    __syncwarp();
    #pragma unroll
    for (int g = 0; g < 2; g++) {
        const int li = w * TOK_PER_WARP + g * 32 + lane;
        const int p = (int)sh_pid[li];
        unsigned m = __match_any_sync(0xffffffffu, p);
        const int rank = __popc(m & ((1u << lane) - 1u));
        const int base = sh_run[w][p];
        __syncwarp();
        if (lane == 31 - __clz(m)) sh_run[w][p] = base + __popc(m);
        __syncwarp();
        const int pos = base + rank;
        if (pos < CAP) g_slot[p * CAP + pos] = blk0 + li;
    }

    // ---- self-clean for deterministic graph replay ----
    __syncthreads();
    if (tid == 0) sh_last = (atomicAdd(&g_done, 1u) == NB - 1);
    __syncthreads();
    if (sh_last) {
        for (int i = tid; i < NB * PATHS; i += TPB) g_desc[i] = 0;
        if (tid == 0) g_done = 0;
    }
}

// Gather: one warp per output row, 4 independent float4s per lane (MLP=4),
// streaming hints (single-use data, keep it out of L2's way).
#define GROWS_PB 16
__global__ __launch_bounds__(512) void k_gather(const float4* __restrict__ in4,
                                                float4* __restrict__ out4) {
    const int w = threadIdx.x >> 5, lane = threadIdx.x & 31;
    const int r = blockIdx.x * GROWS_PB + w;            // output row in [0, P*CAP)
    const int p = r >> 14;                              // r / CAP
    const int j = r & (CAP - 1);                        // r % CAP
    float4 v0 = make_float4(0.f,0.f,0.f,0.f);
    float4 v1 = v0, v2 = v0, v3 = v0;
    if (j < g_cnt[p]) {
        const float4* src = in4 + (size_t)g_slot[r] * D4 + lane;
        v0 = __ldcs(src);
        v1 = __ldcs(src + 32);
        v2 = __ldcs(src + 64);
        v3 = __ldcs(src + 96);
    }
    float4* dst = out4 + (size_t)r * D4 + lane;
    __stcs(dst,      v0);
    __stcs(dst + 32, v1);
    __stcs(dst + 64, v2);
    __stcs(dst + 96, v3);
}

extern "C" void kernel_launch(void* const* d_in, const int* in_sizes, int n_in,
                              void* d_out, int out_size) {
    const float* inputs = (const float*)d_in[0];
    const float* score  = (const float*)d_in[1];
    if (in_sizes[0] == N_TOKENS * PATHS) {   // defensive: identify by element count
        inputs = (const float*)d_in[1];
        score  = (const float*)d_in[0];
    }
    k_route<<<NB, TPB>>>(score);
    k_gather<<<(PATHS * CAP) / GROWS_PB, 512>>>((const float4*)inputs, (float4*)d_out);
}